// round 1
// baseline (speedup 1.0000x reference)
#include <cuda_runtime.h>
#include <math.h>

#define SS 256
#define NH 4
#define HD 32
#define DM 128
#define NROWS (SS*SS)   // 65536

// ---------------- scratch (device globals; no runtime alloc allowed) -------
__device__ float g_xn[(size_t)NROWS * DM];   // layernorm output      32MB
__device__ float g_bm[(size_t)NH * NROWS];   // bias+mask [H,S,S]      1MB
__device__ float g_q [(size_t)NROWS * DM];   // [S,H,S,DH]            32MB
__device__ float g_k [(size_t)NROWS * DM];
__device__ float g_v [(size_t)NROWS * DM];
__device__ float g_g [(size_t)NROWS * DM];   // gate proj [S,S,D]
__device__ float g_o [(size_t)NROWS * DM];   // attn out  [S,S,D]

// ---------------- Kernel A: LayerNorm + (bias projection + mask) -----------
__global__ __launch_bounds__(256)
void ln_bias_kernel(const float* __restrict__ x,
                    const float* __restrict__ mask,
                    const float* __restrict__ lnw,
                    const float* __restrict__ lnb,
                    const float* __restrict__ Wb) {
    int lane = threadIdx.x & 31;
    int row  = blockIdx.x * 8 + (threadIdx.x >> 5);
    const float* xr = x + (size_t)row * DM;

    float v0 = xr[lane], v1 = xr[lane+32], v2 = xr[lane+64], v3 = xr[lane+96];
    float s = v0 + v1 + v2 + v3;
    #pragma unroll
    for (int o = 16; o; o >>= 1) s += __shfl_xor_sync(0xffffffffu, s, o);
    float mu = s * (1.0f/128.0f);
    float d0 = v0-mu, d1 = v1-mu, d2 = v2-mu, d3 = v3-mu;
    float qq = d0*d0 + d1*d1 + d2*d2 + d3*d3;
    #pragma unroll
    for (int o = 16; o; o >>= 1) qq += __shfl_xor_sync(0xffffffffu, qq, o);
    float inv = rsqrtf(qq * (1.0f/128.0f) + 1e-5f);

    float n0 = fmaf(d0*inv, lnw[lane   ], lnb[lane   ]);
    float n1 = fmaf(d1*inv, lnw[lane+32], lnb[lane+32]);
    float n2 = fmaf(d2*inv, lnw[lane+64], lnb[lane+64]);
    float n3 = fmaf(d3*inv, lnw[lane+96], lnb[lane+96]);

    float* xo = g_xn + (size_t)row * DM;
    xo[lane] = n0; xo[lane+32] = n1; xo[lane+64] = n2; xo[lane+96] = n3;

    float mval = mask[row];   // mask index (q,k) == this pair position
    #pragma unroll
    for (int hh = 0; hh < NH; hh++) {
        const float* wb = Wb + hh * DM;
        float dot = n0*wb[lane] + n1*wb[lane+32] + n2*wb[lane+64] + n3*wb[lane+96];
        #pragma unroll
        for (int o = 16; o; o >>= 1) dot += __shfl_xor_sync(0xffffffffu, dot, o);
        if (lane == 0) g_bm[(size_t)hh * NROWS + row] = dot + mval;
    }
}

// ---------------- Kernel B: projections xn @ W^T -> q,k,v,g ----------------
// grid.x: M-tile (64 rows), grid.y: which weight (0=q,1=k,2=v,3=g)
__global__ __launch_bounds__(256)
void proj_kernel(const float* __restrict__ Wq, const float* __restrict__ Wk,
                 const float* __restrict__ Wv, const float* __restrict__ Wg) {
    extern __shared__ float sm[];
    float* As = sm;               // 64  x 129
    float* Bs = sm + 64 * 129;    // 128 x 129

    int w  = blockIdx.y;
    const float* W = (w == 0) ? Wq : (w == 1) ? Wk : (w == 2) ? Wv : Wg;
    int m0  = blockIdx.x * 64;
    int tid = threadIdx.x;

    for (int t = tid; t < 64 * 128; t += 256) {
        int i = t >> 7, j = t & 127;
        As[i * 129 + j] = g_xn[(size_t)(m0 + i) * DM + j];
    }
    for (int t = tid; t < 128 * 128; t += 256) {
        int i = t >> 7, j = t & 127;
        Bs[i * 129 + j] = W[t];
    }
    __syncthreads();

    int tx = tid & 15, ty = tid >> 4;
    float acc[4][8];
    #pragma unroll
    for (int r = 0; r < 4; r++)
        #pragma unroll
        for (int c = 0; c < 8; c++) acc[r][c] = 0.0f;

    #pragma unroll 8
    for (int k = 0; k < 128; k++) {
        float a[4], b[8];
        #pragma unroll
        for (int r = 0; r < 4; r++) a[r] = As[(ty + r * 16) * 129 + k];
        #pragma unroll
        for (int c = 0; c < 8; c++) b[c] = Bs[(tx + c * 16) * 129 + k];
        #pragma unroll
        for (int r = 0; r < 4; r++)
            #pragma unroll
            for (int c = 0; c < 8; c++) acc[r][c] = fmaf(a[r], b[c], acc[r][c]);
    }

    float* dst3 = (w == 0) ? g_q : (w == 1) ? g_k : g_v;
    #pragma unroll
    for (int r = 0; r < 4; r++) {
        int m = m0 + ty + r * 16;
        #pragma unroll
        for (int c = 0; c < 8; c++) {
            int e = tx + c * 16;
            float val = acc[r][c];
            if (w == 3) {
                g_g[(size_t)m * DM + e] = val;
            } else {
                int b  = m >> 8, q = m & 255;
                int h  = e >> 5, dh = e & 31;
                dst3[(((size_t)(b * NH + h)) * SS + q) * HD + dh] = val;
            }
        }
    }
}

// ---------------- Kernel C: attention per (b,h) ----------------------------
__global__ __launch_bounds__(256)
void attn_kernel() {
    extern __shared__ float sm[];
    float*  Ks  = sm;                              // 256 x 33
    float*  Vs  = sm + 256 * 33;                   // 256 x 33
    float4* Ps4 = (float4*)(sm + 2 * 256 * 33);    // 8 warps x 256

    int bh = blockIdx.x;
    int b = bh >> 2, h = bh & 3;
    const float* Kg = g_k + (size_t)bh * (SS * HD);
    const float* Vg = g_v + (size_t)bh * (SS * HD);
    const float* Qg = g_q + (size_t)bh * (SS * HD);

    int tid = threadIdx.x;
    for (int t = tid; t < SS * HD; t += 256) {
        int r = t >> 5, c = t & 31;
        Ks[r * 33 + c] = Kg[t];
        Vs[r * 33 + c] = Vg[t];
    }
    __syncthreads();

    int warp = tid >> 5, lane = tid & 31;
    float4* P = Ps4 + warp * 256;
    const float scale = 0.17677669529663687f;   // 1/sqrt(32)

    for (int g = 0; g < 8; g++) {
        int q0 = warp * 32 + g * 4;
        float qv[4];
        #pragma unroll
        for (int r = 0; r < 4; r++) qv[r] = Qg[(q0 + r) * HD + lane];

        float s[4][8];
        #pragma unroll
        for (int r = 0; r < 4; r++)
            #pragma unroll
            for (int i = 0; i < 8; i++) s[r][i] = 0.0f;

        #pragma unroll
        for (int d = 0; d < 32; d++) {
            float kd[8];
            #pragma unroll
            for (int i = 0; i < 8; i++) kd[i] = Ks[(lane + 32 * i) * 33 + d];
            #pragma unroll
            for (int r = 0; r < 4; r++) {
                float qd = __shfl_sync(0xffffffffu, qv[r], d);
                #pragma unroll
                for (int i = 0; i < 8; i++) s[r][i] = fmaf(qd, kd[i], s[r][i]);
            }
        }

        #pragma unroll
        for (int r = 0; r < 4; r++) {
            const float* bmr = g_bm + (size_t)h * NROWS + (size_t)(q0 + r) * SS;
            float mx = -3.0e38f;
            #pragma unroll
            for (int i = 0; i < 8; i++) {
                s[r][i] = fmaf(s[r][i], scale, bmr[lane + 32 * i]);
                mx = fmaxf(mx, s[r][i]);
            }
            #pragma unroll
            for (int o = 16; o; o >>= 1) mx = fmaxf(mx, __shfl_xor_sync(0xffffffffu, mx, o));
            float sum = 0.0f;
            #pragma unroll
            for (int i = 0; i < 8; i++) { s[r][i] = __expf(s[r][i] - mx); sum += s[r][i]; }
            #pragma unroll
            for (int o = 16; o; o >>= 1) sum += __shfl_xor_sync(0xffffffffu, sum, o);
            float invs = 1.0f / sum;
            #pragma unroll
            for (int i = 0; i < 8; i++) s[r][i] *= invs;
        }

        #pragma unroll
        for (int i = 0; i < 8; i++)
            P[lane + 32 * i] = make_float4(s[0][i], s[1][i], s[2][i], s[3][i]);
        __syncwarp();

        float o0 = 0.f, o1 = 0.f, o2 = 0.f, o3 = 0.f;
        #pragma unroll 8
        for (int k = 0; k < 256; k++) {
            float v = Vs[k * 33 + lane];
            float4 p = P[k];
            o0 = fmaf(p.x, v, o0);
            o1 = fmaf(p.y, v, o1);
            o2 = fmaf(p.z, v, o2);
            o3 = fmaf(p.w, v, o3);
        }
        // g_o layout [S,S,D]: ((b*256+q)*4 + h)*32 + dh ; q -> +128 per row
        float* og = g_o + ((size_t)(b * 256 + q0) * NH + h) * HD + lane;
        og[0]       = o0;
        og[128]     = o1;
        og[256]     = o2;
        og[384]     = o3;
        __syncwarp();
    }
}

// ---------------- Kernel D: out = (o * sigmoid(g)) @ Wo^T ------------------
__global__ __launch_bounds__(256)
void out_kernel(const float* __restrict__ Wo, float* __restrict__ out) {
    extern __shared__ float sm[];
    float* As = sm;               // 64  x 129
    float* Bs = sm + 64 * 129;    // 128 x 129

    int m0  = blockIdx.x * 64;
    int tid = threadIdx.x;

    for (int t = tid; t < 64 * 128; t += 256) {
        int i = t >> 7, j = t & 127;
        size_t gi = (size_t)(m0 + i) * DM + j;
        float gate = g_g[gi];
        float sig  = 1.0f / (1.0f + __expf(-gate));
        As[i * 129 + j] = g_o[gi] * sig;
    }
    for (int t = tid; t < 128 * 128; t += 256) {
        int i = t >> 7, j = t & 127;
        Bs[i * 129 + j] = Wo[t];
    }
    __syncthreads();

    int tx = tid & 15, ty = tid >> 4;
    float acc[4][8];
    #pragma unroll
    for (int r = 0; r < 4; r++)
        #pragma unroll
        for (int c = 0; c < 8; c++) acc[r][c] = 0.0f;

    #pragma unroll 8
    for (int k = 0; k < 128; k++) {
        float a[4], b[8];
        #pragma unroll
        for (int r = 0; r < 4; r++) a[r] = As[(ty + r * 16) * 129 + k];
        #pragma unroll
        for (int c = 0; c < 8; c++) b[c] = Bs[(tx + c * 16) * 129 + k];
        #pragma unroll
        for (int r = 0; r < 4; r++)
            #pragma unroll
            for (int c = 0; c < 8; c++) acc[r][c] = fmaf(a[r], b[c], acc[r][c]);
    }

    #pragma unroll
    for (int r = 0; r < 4; r++) {
        int m = m0 + ty + r * 16;
        #pragma unroll
        for (int c = 0; c < 8; c++) {
            int e = tx + c * 16;
            out[(size_t)m * DM + e] = acc[r][c];
        }
    }
}

// ---------------- launch ----------------------------------------------------
extern "C" void kernel_launch(void* const* d_in, const int* in_sizes, int n_in,
                              void* d_out, int out_size) {
    const float* x    = (const float*)d_in[0];
    const float* mask = (const float*)d_in[1];
    const float* lnw  = (const float*)d_in[2];
    const float* lnb  = (const float*)d_in[3];
    const float* Wb   = (const float*)d_in[4];
    const float* Wq   = (const float*)d_in[5];
    const float* Wk   = (const float*)d_in[6];
    const float* Wv   = (const float*)d_in[7];
    const float* Wg   = (const float*)d_in[8];
    const float* Wo   = (const float*)d_in[9];
    float* out = (float*)d_out;

    const int PROJ_SMEM = (64 * 129 + 128 * 129) * 4;            // 99072 B
    const int ATTN_SMEM = (2 * 256 * 33) * 4 + 8 * 256 * 16;     // 100352 B

    cudaFuncSetAttribute(proj_kernel, cudaFuncAttributeMaxDynamicSharedMemorySize, PROJ_SMEM);
    cudaFuncSetAttribute(out_kernel,  cudaFuncAttributeMaxDynamicSharedMemorySize, PROJ_SMEM);
    cudaFuncSetAttribute(attn_kernel, cudaFuncAttributeMaxDynamicSharedMemorySize, ATTN_SMEM);

    ln_bias_kernel<<<NROWS / 8, 256>>>(x, mask, lnw, lnb, Wb);
    proj_kernel<<<dim3(NROWS / 64, 4), 256, PROJ_SMEM>>>(Wq, Wk, Wv, Wg);
    attn_kernel<<<SS * NH, 256, ATTN_SMEM>>>();
    out_kernel<<<NROWS / 64, 256, PROJ_SMEM>>>(Wo, out);
}

// round 4
// speedup vs baseline: 1.4999x; 1.4999x over previous
#include <cuda_runtime.h>
#include <cstdint>
#include <math.h>

#define SS 256
#define NH 4
#define HD 32
#define DM 128
#define NROWS (SS*SS)   // 65536

// ---------------- scratch (device globals; no runtime alloc allowed) -------
__device__ float g_xn[(size_t)NROWS * DM];   // layernorm output      32MB
__device__ float g_bm[(size_t)NH * NROWS];   // bias+mask [H,S,S]      1MB
__device__ float g_q [(size_t)NROWS * DM];   // [S,H,S,DH]            32MB
__device__ float g_k [(size_t)NROWS * DM];
__device__ float g_v [(size_t)NROWS * DM];
__device__ float g_g [(size_t)NROWS * DM];   // gate proj [S,S,D]
__device__ float g_o [(size_t)NROWS * DM];   // attn out  [S,S,D]

// single extern shared symbol for the whole TU
extern __shared__ char smem_raw[];

__device__ __forceinline__ uint32_t f2tf32(float f) {
    uint32_t u;
    asm("cvt.rna.tf32.f32 %0, %1;" : "=r"(u) : "f"(f));
    return u;
}

// mma.sync m16n8k8 tf32: D[16x8] += A[16x8] * B[8x8]; standard PTX (sm_80+),
// valid on plain compute_103 virtual arch (tcgen05 is NOT - 'a'-target only).
__device__ __forceinline__ void mma_tf32(float4& d,
                                         uint32_t a0, uint32_t a1, uint32_t a2, uint32_t a3,
                                         uint32_t b0, uint32_t b1) {
    asm volatile(
        "mma.sync.aligned.m16n8k8.row.col.f32.tf32.tf32.f32 "
        "{%0,%1,%2,%3}, {%4,%5,%6,%7}, {%8,%9}, {%0,%1,%2,%3};"
        : "+f"(d.x), "+f"(d.y), "+f"(d.z), "+f"(d.w)
        : "r"(a0), "r"(a1), "r"(a2), "r"(a3), "r"(b0), "r"(b1));
}

// ---------------- Kernel A: LayerNorm + (bias projection + mask) -----------
__global__ __launch_bounds__(256)
void ln_bias_kernel(const float* __restrict__ x,
                    const float* __restrict__ mask,
                    const float* __restrict__ lnw,
                    const float* __restrict__ lnb,
                    const float* __restrict__ Wb) {
    int lane = threadIdx.x & 31;
    int row  = blockIdx.x * 8 + (threadIdx.x >> 5);
    const float* xr = x + (size_t)row * DM;

    float v0 = xr[lane], v1 = xr[lane+32], v2 = xr[lane+64], v3 = xr[lane+96];
    float s = v0 + v1 + v2 + v3;
    #pragma unroll
    for (int o = 16; o; o >>= 1) s += __shfl_xor_sync(0xffffffffu, s, o);
    float mu = s * (1.0f/128.0f);
    float d0 = v0-mu, d1 = v1-mu, d2 = v2-mu, d3 = v3-mu;
    float qq = d0*d0 + d1*d1 + d2*d2 + d3*d3;
    #pragma unroll
    for (int o = 16; o; o >>= 1) qq += __shfl_xor_sync(0xffffffffu, qq, o);
    float inv = rsqrtf(qq * (1.0f/128.0f) + 1e-5f);

    float n0 = fmaf(d0*inv, lnw[lane   ], lnb[lane   ]);
    float n1 = fmaf(d1*inv, lnw[lane+32], lnb[lane+32]);
    float n2 = fmaf(d2*inv, lnw[lane+64], lnb[lane+64]);
    float n3 = fmaf(d3*inv, lnw[lane+96], lnb[lane+96]);

    float* xo = g_xn + (size_t)row * DM;
    xo[lane] = n0; xo[lane+32] = n1; xo[lane+64] = n2; xo[lane+96] = n3;

    float mval = mask[row];
    #pragma unroll
    for (int hh = 0; hh < NH; hh++) {
        const float* wb = Wb + hh * DM;
        float dot = n0*wb[lane] + n1*wb[lane+32] + n2*wb[lane+64] + n3*wb[lane+96];
        #pragma unroll
        for (int o = 16; o; o >>= 1) dot += __shfl_xor_sync(0xffffffffu, dot, o);
        if (lane == 0) g_bm[(size_t)hh * NROWS + row] = dot + mval;
    }
}

// ---------------- Kernel B: mma.sync tf32 GEMM ------------------------------
// out[m][e] = sum_k A[m][k] * W[e][k]   (A tile 128 rows, W 128x128)
// mode 0: 4 rounds (q,k,v,g) from g_xn.  mode 1: 1 round, A = g_o*sigmoid(g_g), W = Wo.
#define LDA 132   // padded row stride (floats) -> conflict-free frag loads
#define GEMM_SMEM (2 * 128 * LDA * 4)

__global__ __launch_bounds__(256, 1)
void gemm_tf32_kernel(const float* __restrict__ Wq, const float* __restrict__ Wk,
                      const float* __restrict__ Wv, const float* __restrict__ Wg,
                      const float* __restrict__ Wo, float* __restrict__ out, int mode) {
    uint32_t* As = (uint32_t*)smem_raw;        // [128][LDA] tf32
    uint32_t* Ws = As + 128 * LDA;             // [128][LDA] tf32 (row e, col k)

    int tid = threadIdx.x, wid = tid >> 5, lane = tid & 31;
    int m0 = blockIdx.x * 128;
    int lr = lane >> 2, lc = lane & 3;       // fragment row/col within 8x4
    int wr = wid & 3;                        // M chunk of 32 (4 chunks)
    int wc = wid >> 2;                       // N chunk of 64 (2 chunks)

    // ---- stage A tile (tf32-rounded) ----
    if (mode == 0) {
        #pragma unroll
        for (int t = tid; t < 128 * 32; t += 256) {
            int row = t >> 5, c4 = (t & 31) * 4;
            float4 v = *(const float4*)(g_xn + (size_t)(m0 + row) * DM + c4);
            uint32_t* d = As + row * LDA + c4;
            d[0] = f2tf32(v.x); d[1] = f2tf32(v.y); d[2] = f2tf32(v.z); d[3] = f2tf32(v.w);
        }
    } else {
        #pragma unroll
        for (int t = tid; t < 128 * 32; t += 256) {
            int row = t >> 5, c4 = (t & 31) * 4;
            size_t gi = (size_t)(m0 + row) * DM + c4;
            float4 ov = *(const float4*)(g_o + gi);
            float4 gv = *(const float4*)(g_g + gi);
            uint32_t* d = As + row * LDA + c4;
            d[0] = f2tf32(ov.x / (1.0f + __expf(-gv.x)));
            d[1] = f2tf32(ov.y / (1.0f + __expf(-gv.y)));
            d[2] = f2tf32(ov.z / (1.0f + __expf(-gv.z)));
            d[3] = f2tf32(ov.w / (1.0f + __expf(-gv.w)));
        }
    }

    const float* Wsrc[4] = {Wq, Wk, Wv, Wg};
    int nW = (mode == 0) ? 4 : 1;

    for (int w = 0; w < nW; w++) {
        const float* W = (mode == 1) ? Wo : Wsrc[w];
        #pragma unroll
        for (int t = tid; t < 128 * 32; t += 256) {
            int row = t >> 5, c4 = (t & 31) * 4;
            float4 v = *(const float4*)(W + (size_t)row * DM + c4);
            uint32_t* d = Ws + row * LDA + c4;
            d[0] = f2tf32(v.x); d[1] = f2tf32(v.y); d[2] = f2tf32(v.z); d[3] = f2tf32(v.w);
        }
        __syncthreads();

        // ---- 32x64 warp tile: 2 m-frags x 8 n-frags, K=128 in 16 steps ----
        float4 acc[2][8];
        #pragma unroll
        for (int mt = 0; mt < 2; mt++)
            #pragma unroll
            for (int nt = 0; nt < 8; nt++) acc[mt][nt] = make_float4(0.f, 0.f, 0.f, 0.f);

        const uint32_t* Ab = As + (wr * 32 + lr) * LDA + lc;
        const uint32_t* Bb = Ws + (wc * 64 + lr) * LDA + lc;

        #pragma unroll
        for (int ks = 0; ks < 16; ks++) {
            int k0 = ks * 8;
            uint32_t a[2][4], b[8][2];
            #pragma unroll
            for (int mt = 0; mt < 2; mt++) {
                const uint32_t* p = Ab + mt * 16 * LDA + k0;
                a[mt][0] = p[0];
                a[mt][1] = p[8 * LDA];
                a[mt][2] = p[4];
                a[mt][3] = p[8 * LDA + 4];
            }
            #pragma unroll
            for (int nt = 0; nt < 8; nt++) {
                const uint32_t* p = Bb + nt * 8 * LDA + k0;
                b[nt][0] = p[0];
                b[nt][1] = p[4];
            }
            #pragma unroll
            for (int mt = 0; mt < 2; mt++)
                #pragma unroll
                for (int nt = 0; nt < 8; nt++)
                    mma_tf32(acc[mt][nt], a[mt][0], a[mt][1], a[mt][2], a[mt][3],
                             b[nt][0], b[nt][1]);
        }

        // ---- epilogue: direct register -> global stores ----
        #pragma unroll
        for (int mt = 0; mt < 2; mt++) {
            int m = m0 + wr * 32 + mt * 16 + lr;     // and m+8
            #pragma unroll
            for (int nt = 0; nt < 8; nt++) {
                int e = wc * 64 + nt * 8 + 2 * lc;   // pair (e, e+1)
                float2 lo = make_float2(acc[mt][nt].x, acc[mt][nt].y);
                float2 hi = make_float2(acc[mt][nt].z, acc[mt][nt].w);
                if (mode == 1) {
                    *(float2*)(out + (size_t)m * DM + e)       = lo;
                    *(float2*)(out + (size_t)(m + 8) * DM + e) = hi;
                } else if (w == 3) {
                    *(float2*)(g_g + (size_t)m * DM + e)       = lo;
                    *(float2*)(g_g + (size_t)(m + 8) * DM + e) = hi;
                } else {
                    float* dst3 = (w == 0) ? g_q : (w == 1) ? g_k : g_v;
                    int h = e >> 5, dh = e & 31;
                    int b0i = m >> 8, q0i = m & 255;
                    int b1i = (m + 8) >> 8, q1i = (m + 8) & 255;
                    *(float2*)(dst3 + (((size_t)(b0i * NH + h)) * SS + q0i) * HD + dh) = lo;
                    *(float2*)(dst3 + (((size_t)(b1i * NH + h)) * SS + q1i) * HD + dh) = hi;
                }
            }
        }
        __syncthreads();
    }
}

// ---------------- Kernel C: attention per (b,h) ----------------------------
__global__ __launch_bounds__(256)
void attn_kernel() {
    float* sm = (float*)smem_raw;
    float*  Ks  = sm;                              // 256 x 33
    float*  Vs  = sm + 256 * 33;                   // 256 x 33
    float4* Ps4 = (float4*)(sm + 2 * 256 * 33);    // 8 warps x 256

    int bh = blockIdx.x;
    int b = bh >> 2, h = bh & 3;
    const float* Kg = g_k + (size_t)bh * (SS * HD);
    const float* Vg = g_v + (size_t)bh * (SS * HD);
    const float* Qg = g_q + (size_t)bh * (SS * HD);

    int tid = threadIdx.x;
    for (int t = tid; t < SS * HD; t += 256) {
        int r = t >> 5, c = t & 31;
        Ks[r * 33 + c] = Kg[t];
        Vs[r * 33 + c] = Vg[t];
    }
    __syncthreads();

    int warp = tid >> 5, lane = tid & 31;
    float4* P = Ps4 + warp * 256;
    const float scale = 0.17677669529663687f;   // 1/sqrt(32)

    for (int g = 0; g < 8; g++) {
        int q0 = warp * 32 + g * 4;
        float qv[4];
        #pragma unroll
        for (int r = 0; r < 4; r++) qv[r] = Qg[(q0 + r) * HD + lane];

        float s[4][8];
        #pragma unroll
        for (int r = 0; r < 4; r++)
            #pragma unroll
            for (int i = 0; i < 8; i++) s[r][i] = 0.0f;

        #pragma unroll
        for (int d = 0; d < 32; d++) {
            float kd[8];
            #pragma unroll
            for (int i = 0; i < 8; i++) kd[i] = Ks[(lane + 32 * i) * 33 + d];
            #pragma unroll
            for (int r = 0; r < 4; r++) {
                float qd = __shfl_sync(0xffffffffu, qv[r], d);
                #pragma unroll
                for (int i = 0; i < 8; i++) s[r][i] = fmaf(qd, kd[i], s[r][i]);
            }
        }

        #pragma unroll
        for (int r = 0; r < 4; r++) {
            const float* bmr = g_bm + (size_t)h * NROWS + (size_t)(q0 + r) * SS;
            float mx = -3.0e38f;
            #pragma unroll
            for (int i = 0; i < 8; i++) {
                s[r][i] = fmaf(s[r][i], scale, bmr[lane + 32 * i]);
                mx = fmaxf(mx, s[r][i]);
            }
            #pragma unroll
            for (int o = 16; o; o >>= 1) mx = fmaxf(mx, __shfl_xor_sync(0xffffffffu, mx, o));
            float sum = 0.0f;
            #pragma unroll
            for (int i = 0; i < 8; i++) { s[r][i] = __expf(s[r][i] - mx); sum += s[r][i]; }
            #pragma unroll
            for (int o = 16; o; o >>= 1) sum += __shfl_xor_sync(0xffffffffu, sum, o);
            float invs = 1.0f / sum;
            #pragma unroll
            for (int i = 0; i < 8; i++) s[r][i] *= invs;
        }

        #pragma unroll
        for (int i = 0; i < 8; i++)
            P[lane + 32 * i] = make_float4(s[0][i], s[1][i], s[2][i], s[3][i]);
        __syncwarp();

        float o0 = 0.f, o1 = 0.f, o2 = 0.f, o3 = 0.f;
        #pragma unroll 8
        for (int k = 0; k < 256; k++) {
            float v = Vs[k * 33 + lane];
            float4 p = P[k];
            o0 = fmaf(p.x, v, o0);
            o1 = fmaf(p.y, v, o1);
            o2 = fmaf(p.z, v, o2);
            o3 = fmaf(p.w, v, o3);
        }
        float* og = g_o + ((size_t)(b * 256 + q0) * NH + h) * HD + lane;
        og[0]   = o0;
        og[128] = o1;
        og[256] = o2;
        og[384] = o3;
        __syncwarp();
    }
}

// ---------------- launch ----------------------------------------------------
extern "C" void kernel_launch(void* const* d_in, const int* in_sizes, int n_in,
                              void* d_out, int out_size) {
    const float* x    = (const float*)d_in[0];
    const float* mask = (const float*)d_in[1];
    const float* lnw  = (const float*)d_in[2];
    const float* lnb  = (const float*)d_in[3];
    const float* Wb   = (const float*)d_in[4];
    const float* Wq   = (const float*)d_in[5];
    const float* Wk   = (const float*)d_in[6];
    const float* Wv   = (const float*)d_in[7];
    const float* Wg   = (const float*)d_in[8];
    const float* Wo   = (const float*)d_in[9];
    float* out = (float*)d_out;

    const int ATTN_SMEM = (2 * 256 * 33) * 4 + 8 * 256 * 16;     // 100352 B

    cudaFuncSetAttribute(gemm_tf32_kernel, cudaFuncAttributeMaxDynamicSharedMemorySize, GEMM_SMEM);
    cudaFuncSetAttribute(attn_kernel, cudaFuncAttributeMaxDynamicSharedMemorySize, ATTN_SMEM);

    ln_bias_kernel<<<NROWS / 8, 256>>>(x, mask, lnw, lnb, Wb);
    gemm_tf32_kernel<<<NROWS / 128, 256, GEMM_SMEM>>>(Wq, Wk, Wv, Wg, Wo, out, 0);
    attn_kernel<<<SS * NH, 256, ATTN_SMEM>>>();
    gemm_tf32_kernel<<<NROWS / 128, 256, GEMM_SMEM>>>(Wq, Wk, Wv, Wg, Wo, out, 1);
}

// round 5
// speedup vs baseline: 1.5809x; 1.0541x over previous
#include <cuda_runtime.h>
#include <cstdint>
#include <math.h>

#define SS 256
#define NH 4
#define HD 32
#define DM 128
#define NROWS (SS*SS)   // 65536

// ---------------- scratch (device globals; no runtime alloc allowed) -------
__device__ float g_xn[(size_t)NROWS * DM];   // layernorm output      32MB
__device__ float g_bm[(size_t)NH * NROWS];   // bias+mask [H,S,S]      1MB
__device__ float g_q [(size_t)NROWS * DM];   // [S,H,S,DH]            32MB
__device__ float g_k [(size_t)NROWS * DM];
__device__ float g_v [(size_t)NROWS * DM];
__device__ float g_g [(size_t)NROWS * DM];   // gate proj [S,S,D]
__device__ float g_o [(size_t)NROWS * DM];   // attn out  [S,S,D]

// single extern shared symbol for the whole TU
extern __shared__ char smem_raw[];

__device__ __forceinline__ uint32_t f2tf32(float f) {
    uint32_t u;
    asm("cvt.rna.tf32.f32 %0, %1;" : "=r"(u) : "f"(f));
    return u;
}

// mma.sync m16n8k8 tf32 (sm_80+ PTX; valid on plain compute_103)
__device__ __forceinline__ void mma_tf32(float4& d,
                                         uint32_t a0, uint32_t a1, uint32_t a2, uint32_t a3,
                                         uint32_t b0, uint32_t b1) {
    asm volatile(
        "mma.sync.aligned.m16n8k8.row.col.f32.tf32.tf32.f32 "
        "{%0,%1,%2,%3}, {%4,%5,%6,%7}, {%8,%9}, {%0,%1,%2,%3};"
        : "+f"(d.x), "+f"(d.y), "+f"(d.z), "+f"(d.w)
        : "r"(a0), "r"(a1), "r"(a2), "r"(a3), "r"(b0), "r"(b1));
}

// ---------------- Kernel A: LayerNorm + (bias projection + mask) -----------
__global__ __launch_bounds__(256)
void ln_bias_kernel(const float* __restrict__ x,
                    const float* __restrict__ mask,
                    const float* __restrict__ lnw,
                    const float* __restrict__ lnb,
                    const float* __restrict__ Wb) {
    int lane = threadIdx.x & 31;
    int row  = blockIdx.x * 8 + (threadIdx.x >> 5);
    const float* xr = x + (size_t)row * DM;

    float v0 = xr[lane], v1 = xr[lane+32], v2 = xr[lane+64], v3 = xr[lane+96];
    float s = v0 + v1 + v2 + v3;
    #pragma unroll
    for (int o = 16; o; o >>= 1) s += __shfl_xor_sync(0xffffffffu, s, o);
    float mu = s * (1.0f/128.0f);
    float d0 = v0-mu, d1 = v1-mu, d2 = v2-mu, d3 = v3-mu;
    float qq = d0*d0 + d1*d1 + d2*d2 + d3*d3;
    #pragma unroll
    for (int o = 16; o; o >>= 1) qq += __shfl_xor_sync(0xffffffffu, qq, o);
    float inv = rsqrtf(qq * (1.0f/128.0f) + 1e-5f);

    float n0 = fmaf(d0*inv, lnw[lane   ], lnb[lane   ]);
    float n1 = fmaf(d1*inv, lnw[lane+32], lnb[lane+32]);
    float n2 = fmaf(d2*inv, lnw[lane+64], lnb[lane+64]);
    float n3 = fmaf(d3*inv, lnw[lane+96], lnb[lane+96]);

    float* xo = g_xn + (size_t)row * DM;
    xo[lane] = n0; xo[lane+32] = n1; xo[lane+64] = n2; xo[lane+96] = n3;

    float mval = mask[row];
    #pragma unroll
    for (int hh = 0; hh < NH; hh++) {
        const float* wb = Wb + hh * DM;
        float dot = n0*wb[lane] + n1*wb[lane+32] + n2*wb[lane+64] + n3*wb[lane+96];
        #pragma unroll
        for (int o = 16; o; o >>= 1) dot += __shfl_xor_sync(0xffffffffu, dot, o);
        if (lane == 0) g_bm[(size_t)hh * NROWS + row] = dot + mval;
    }
}

// ---------------- Kernel B: mma.sync tf32 GEMM ------------------------------
#define LDA 132
#define GEMM_SMEM (2 * 128 * LDA * 4)

__global__ __launch_bounds__(256, 1)
void gemm_tf32_kernel(const float* __restrict__ Wq, const float* __restrict__ Wk,
                      const float* __restrict__ Wv, const float* __restrict__ Wg,
                      const float* __restrict__ Wo, float* __restrict__ out, int mode) {
    uint32_t* As = (uint32_t*)smem_raw;        // [128][LDA] tf32
    uint32_t* Ws = As + 128 * LDA;             // [128][LDA] tf32

    int tid = threadIdx.x, wid = tid >> 5, lane = tid & 31;
    int m0 = blockIdx.x * 128;
    int lr = lane >> 2, lc = lane & 3;
    int wr = wid & 3;
    int wc = wid >> 2;

    if (mode == 0) {
        #pragma unroll
        for (int t = tid; t < 128 * 32; t += 256) {
            int row = t >> 5, c4 = (t & 31) * 4;
            float4 v = *(const float4*)(g_xn + (size_t)(m0 + row) * DM + c4);
            uint32_t* d = As + row * LDA + c4;
            d[0] = f2tf32(v.x); d[1] = f2tf32(v.y); d[2] = f2tf32(v.z); d[3] = f2tf32(v.w);
        }
    } else {
        #pragma unroll
        for (int t = tid; t < 128 * 32; t += 256) {
            int row = t >> 5, c4 = (t & 31) * 4;
            size_t gi = (size_t)(m0 + row) * DM + c4;
            float4 ov = *(const float4*)(g_o + gi);
            float4 gv = *(const float4*)(g_g + gi);
            uint32_t* d = As + row * LDA + c4;
            d[0] = f2tf32(ov.x / (1.0f + __expf(-gv.x)));
            d[1] = f2tf32(ov.y / (1.0f + __expf(-gv.y)));
            d[2] = f2tf32(ov.z / (1.0f + __expf(-gv.z)));
            d[3] = f2tf32(ov.w / (1.0f + __expf(-gv.w)));
        }
    }

    const float* Wsrc[4] = {Wq, Wk, Wv, Wg};
    int nW = (mode == 0) ? 4 : 1;

    for (int w = 0; w < nW; w++) {
        const float* W = (mode == 1) ? Wo : Wsrc[w];
        #pragma unroll
        for (int t = tid; t < 128 * 32; t += 256) {
            int row = t >> 5, c4 = (t & 31) * 4;
            float4 v = *(const float4*)(W + (size_t)row * DM + c4);
            uint32_t* d = Ws + row * LDA + c4;
            d[0] = f2tf32(v.x); d[1] = f2tf32(v.y); d[2] = f2tf32(v.z); d[3] = f2tf32(v.w);
        }
        __syncthreads();

        float4 acc[2][8];
        #pragma unroll
        for (int mt = 0; mt < 2; mt++)
            #pragma unroll
            for (int nt = 0; nt < 8; nt++) acc[mt][nt] = make_float4(0.f, 0.f, 0.f, 0.f);

        const uint32_t* Ab = As + (wr * 32 + lr) * LDA + lc;
        const uint32_t* Bb = Ws + (wc * 64 + lr) * LDA + lc;

        #pragma unroll
        for (int ks = 0; ks < 16; ks++) {
            int k0 = ks * 8;
            uint32_t a[2][4], b[8][2];
            #pragma unroll
            for (int mt = 0; mt < 2; mt++) {
                const uint32_t* p = Ab + mt * 16 * LDA + k0;
                a[mt][0] = p[0];
                a[mt][1] = p[8 * LDA];
                a[mt][2] = p[4];
                a[mt][3] = p[8 * LDA + 4];
            }
            #pragma unroll
            for (int nt = 0; nt < 8; nt++) {
                const uint32_t* p = Bb + nt * 8 * LDA + k0;
                b[nt][0] = p[0];
                b[nt][1] = p[4];
            }
            #pragma unroll
            for (int mt = 0; mt < 2; mt++)
                #pragma unroll
                for (int nt = 0; nt < 8; nt++)
                    mma_tf32(acc[mt][nt], a[mt][0], a[mt][1], a[mt][2], a[mt][3],
                             b[nt][0], b[nt][1]);
        }

        #pragma unroll
        for (int mt = 0; mt < 2; mt++) {
            int m = m0 + wr * 32 + mt * 16 + lr;
            #pragma unroll
            for (int nt = 0; nt < 8; nt++) {
                int e = wc * 64 + nt * 8 + 2 * lc;
                float2 lo = make_float2(acc[mt][nt].x, acc[mt][nt].y);
                float2 hi = make_float2(acc[mt][nt].z, acc[mt][nt].w);
                if (mode == 1) {
                    *(float2*)(out + (size_t)m * DM + e)       = lo;
                    *(float2*)(out + (size_t)(m + 8) * DM + e) = hi;
                } else if (w == 3) {
                    *(float2*)(g_g + (size_t)m * DM + e)       = lo;
                    *(float2*)(g_g + (size_t)(m + 8) * DM + e) = hi;
                } else {
                    float* dst3 = (w == 0) ? g_q : (w == 1) ? g_k : g_v;
                    int h = e >> 5, dh = e & 31;
                    int b0i = m >> 8, q0i = m & 255;
                    int b1i = (m + 8) >> 8, q1i = (m + 8) & 255;
                    *(float2*)(dst3 + (((size_t)(b0i * NH + h)) * SS + q0i) * HD + dh) = lo;
                    *(float2*)(dst3 + (((size_t)(b1i * NH + h)) * SS + q1i) * HD + dh) = hi;
                }
            }
        }
        __syncthreads();
    }
}

// ---------------- Kernel C: tf32 mma attention per (b,h) -------------------
// smem (float/uint element offsets):
//   Qs  [64][36]   scaled fp32      @ 0      (2304)
//   Ksh [256][36]  tf32 hi          @ 2304   (9216)
//   Ksl [256][36]  tf32 lo          @ 11520  (9216)
//   Vth [32][260]  V^T tf32 hi      @ 20736  (8320)
//   Vtl [32][260]  V^T tf32 lo      @ 29056  (8320)
//   Ss  [64][260]  scores / P fp32  @ 37376  (16640)
#define ATTN_SMEM (54016 * 4)

__global__ __launch_bounds__(256, 1)
void attn_mma_kernel() {
    float*    smf = (float*)smem_raw;
    uint32_t* smu = (uint32_t*)smem_raw;
    float*    Qs  = smf;
    uint32_t* Ksh = smu + 2304;
    uint32_t* Ksl = smu + 11520;
    uint32_t* Vth = smu + 20736;
    uint32_t* Vtl = smu + 29056;
    float*    Ss  = smf + 37376;

    int bh = blockIdx.x, b = bh >> 2, h = bh & 3;
    const float* Qg = g_q + (size_t)bh * (SS * HD);
    const float* Kg = g_k + (size_t)bh * (SS * HD);
    const float* Vg = g_v + (size_t)bh * (SS * HD);

    int tid = threadIdx.x, warp = tid >> 5, lane = tid & 31;
    int lr = lane >> 2, lc = lane & 3;

    // stage K hi/lo and V^T hi/lo (once per block)
    for (int i = tid; i < SS * HD; i += 256) {
        int key = i >> 5, d = i & 31;
        float kv = Kg[i];
        uint32_t khi = f2tf32(kv);
        Ksh[key * 36 + d] = khi;
        Ksl[key * 36 + d] = f2tf32(kv - __uint_as_float(khi));
        float vv = Vg[i];
        uint32_t vhi = f2tf32(vv);
        Vth[d * 260 + key] = vhi;
        Vtl[d * 260 + key] = f2tf32(vv - __uint_as_float(vhi));
    }

    for (int qt = 0; qt < 4; qt++) {
        __syncthreads();   // K/V staged (iter 0); prev-iter PV done with Ss
        // stage Q tile, pre-scaled by 1/sqrt(DH)
        for (int i = tid; i < 64 * HD; i += 256) {
            int r = i >> 5, d = i & 31;
            Qs[r * 36 + d] = Qg[(qt * 64 + r) * HD + d] * 0.17677669529663687f;
        }
        __syncthreads();

        // ---- S = Q K^T  (3-pass 3xTF32: fp32-accurate) ----
        {
            int mbase = (warp & 3) * 16;
            int nbase = (warp >> 2) * 128;
            float4 acc[16];
            #pragma unroll
            for (int i = 0; i < 16; i++) acc[i] = make_float4(0.f, 0.f, 0.f, 0.f);
            #pragma unroll
            for (int ks = 0; ks < 4; ks++) {
                int k0 = ks * 8;
                float a0 = Qs[(mbase + lr) * 36 + k0 + lc];
                float a1 = Qs[(mbase + lr + 8) * 36 + k0 + lc];
                float a2 = Qs[(mbase + lr) * 36 + k0 + lc + 4];
                float a3 = Qs[(mbase + lr + 8) * 36 + k0 + lc + 4];
                uint32_t ah0 = f2tf32(a0), ah1 = f2tf32(a1), ah2 = f2tf32(a2), ah3 = f2tf32(a3);
                uint32_t al0 = f2tf32(a0 - __uint_as_float(ah0));
                uint32_t al1 = f2tf32(a1 - __uint_as_float(ah1));
                uint32_t al2 = f2tf32(a2 - __uint_as_float(ah2));
                uint32_t al3 = f2tf32(a3 - __uint_as_float(ah3));
                #pragma unroll
                for (int nf = 0; nf < 16; nf++) {
                    int bi = (nbase + nf * 8 + lr) * 36 + k0 + lc;
                    uint32_t bh0 = Ksh[bi], bh1 = Ksh[bi + 4];
                    uint32_t bl0 = Ksl[bi], bl1 = Ksl[bi + 4];
                    mma_tf32(acc[nf], ah0, ah1, ah2, ah3, bh0, bh1);
                    mma_tf32(acc[nf], ah0, ah1, ah2, ah3, bl0, bl1);
                    mma_tf32(acc[nf], al0, al1, al2, al3, bh0, bh1);
                }
            }
            #pragma unroll
            for (int nf = 0; nf < 16; nf++) {
                int col = nbase + nf * 8 + 2 * lc;
                *(float2*)&Ss[(mbase + lr) * 260 + col]     = make_float2(acc[nf].x, acc[nf].y);
                *(float2*)&Ss[(mbase + lr + 8) * 260 + col] = make_float2(acc[nf].z, acc[nf].w);
            }
        }
        __syncthreads();

        // ---- softmax (rows warp*8 .. +7), bias+mask added here ----
        for (int rr = 0; rr < 8; rr++) {
            int r = warp * 8 + rr;
            int q = qt * 64 + r;
            const float* bmr = g_bm + (size_t)h * NROWS + (size_t)q * SS;
            float sv[8];
            float mx = -3.0e38f;
            #pragma unroll
            for (int j = 0; j < 8; j++) {
                sv[j] = Ss[r * 260 + lane + 32 * j] + bmr[lane + 32 * j];
                mx = fmaxf(mx, sv[j]);
            }
            #pragma unroll
            for (int o = 16; o; o >>= 1) mx = fmaxf(mx, __shfl_xor_sync(0xffffffffu, mx, o));
            float sum = 0.f;
            #pragma unroll
            for (int j = 0; j < 8; j++) { sv[j] = __expf(sv[j] - mx); sum += sv[j]; }
            #pragma unroll
            for (int o = 16; o; o >>= 1) sum += __shfl_xor_sync(0xffffffffu, sum, o);
            float inv = 1.0f / sum;
            #pragma unroll
            for (int j = 0; j < 8; j++) Ss[r * 260 + lane + 32 * j] = sv[j] * inv;
        }
        __syncthreads();

        // ---- O = P V  (2-pass: P*Vh + P*Vl) ----
        {
            int mbase = (warp & 3) * 16;
            int nb = (warp >> 2) * 16;
            float4 acc0 = make_float4(0.f, 0.f, 0.f, 0.f);
            float4 acc1 = make_float4(0.f, 0.f, 0.f, 0.f);
            #pragma unroll 4
            for (int ks = 0; ks < 32; ks++) {
                int k0 = ks * 8;
                uint32_t a0 = f2tf32(Ss[(mbase + lr) * 260 + k0 + lc]);
                uint32_t a1 = f2tf32(Ss[(mbase + lr + 8) * 260 + k0 + lc]);
                uint32_t a2 = f2tf32(Ss[(mbase + lr) * 260 + k0 + lc + 4]);
                uint32_t a3 = f2tf32(Ss[(mbase + lr + 8) * 260 + k0 + lc + 4]);
                int b0i = (nb + lr) * 260 + k0 + lc;
                int b1i = (nb + 8 + lr) * 260 + k0 + lc;
                mma_tf32(acc0, a0, a1, a2, a3, Vth[b0i], Vth[b0i + 4]);
                mma_tf32(acc0, a0, a1, a2, a3, Vtl[b0i], Vtl[b0i + 4]);
                mma_tf32(acc1, a0, a1, a2, a3, Vth[b1i], Vth[b1i + 4]);
                mma_tf32(acc1, a0, a1, a2, a3, Vtl[b1i], Vtl[b1i + 4]);
            }
            int q0 = qt * 64 + mbase + lr;
            float* o0p = g_o + ((size_t)(b * 256 + q0) * NH + h) * HD;
            float* o1p = g_o + ((size_t)(b * 256 + q0 + 8) * NH + h) * HD;
            *(float2*)(o0p + nb + 2 * lc)     = make_float2(acc0.x, acc0.y);
            *(float2*)(o1p + nb + 2 * lc)     = make_float2(acc0.z, acc0.w);
            *(float2*)(o0p + nb + 8 + 2 * lc) = make_float2(acc1.x, acc1.y);
            *(float2*)(o1p + nb + 8 + 2 * lc) = make_float2(acc1.z, acc1.w);
        }
    }
}

// ---------------- launch ----------------------------------------------------
extern "C" void kernel_launch(void* const* d_in, const int* in_sizes, int n_in,
                              void* d_out, int out_size) {
    const float* x    = (const float*)d_in[0];
    const float* mask = (const float*)d_in[1];
    const float* lnw  = (const float*)d_in[2];
    const float* lnb  = (const float*)d_in[3];
    const float* Wb   = (const float*)d_in[4];
    const float* Wq   = (const float*)d_in[5];
    const float* Wk   = (const float*)d_in[6];
    const float* Wv   = (const float*)d_in[7];
    const float* Wg   = (const float*)d_in[8];
    const float* Wo   = (const float*)d_in[9];
    float* out = (float*)d_out;

    cudaFuncSetAttribute(gemm_tf32_kernel, cudaFuncAttributeMaxDynamicSharedMemorySize, GEMM_SMEM);
    cudaFuncSetAttribute(attn_mma_kernel,  cudaFuncAttributeMaxDynamicSharedMemorySize, ATTN_SMEM);

    ln_bias_kernel<<<NROWS / 8, 256>>>(x, mask, lnw, lnb, Wb);
    gemm_tf32_kernel<<<NROWS / 128, 256, GEMM_SMEM>>>(Wq, Wk, Wv, Wg, Wo, out, 0);
    attn_mma_kernel<<<SS * NH, 256, ATTN_SMEM>>>();
    gemm_tf32_kernel<<<NROWS / 128, 256, GEMM_SMEM>>>(Wq, Wk, Wv, Wg, Wo, out, 1);
}

// round 6
// speedup vs baseline: 2.3042x; 1.4575x over previous
#include <cuda_runtime.h>
#include <cuda_fp16.h>
#include <cstdint>
#include <math.h>

#define SS 256
#define NH 4
#define HD 32
#define DM 128
#define NROWS (SS*SS)   // 65536

// ---------------- scratch (device globals; no runtime alloc allowed) -------
__device__ float g_xn[(size_t)NROWS * DM];   // layernorm output      32MB
__device__ float g_bm[(size_t)NH * NROWS];   // bias+mask [H,S,S]      1MB
__device__ float g_q [(size_t)NROWS * DM];   // [S,H,S,DH]            32MB
__device__ float g_k [(size_t)NROWS * DM];
__device__ float g_v [(size_t)NROWS * DM];
__device__ float g_g [(size_t)NROWS * DM];   // gate proj [S,S,D]
__device__ float g_o [(size_t)NROWS * DM];   // attn out  [S,S,D]

// single extern shared symbol for the whole TU
extern __shared__ char smem_raw[];

__device__ __forceinline__ uint32_t f2tf32(float f) {
    uint32_t u;
    asm("cvt.rna.tf32.f32 %0, %1;" : "=r"(u) : "f"(f));
    return u;
}

// mma.sync m16n8k8 tf32 (sm_80+ PTX; valid on plain compute_103)
__device__ __forceinline__ void mma_tf32(float4& d,
                                         uint32_t a0, uint32_t a1, uint32_t a2, uint32_t a3,
                                         uint32_t b0, uint32_t b1) {
    asm volatile(
        "mma.sync.aligned.m16n8k8.row.col.f32.tf32.tf32.f32 "
        "{%0,%1,%2,%3}, {%4,%5,%6,%7}, {%8,%9}, {%0,%1,%2,%3};"
        : "+f"(d.x), "+f"(d.y), "+f"(d.z), "+f"(d.w)
        : "r"(a0), "r"(a1), "r"(a2), "r"(a3), "r"(b0), "r"(b1));
}

// mma.sync m16n8k16 fp16 with fp32 accumulate
__device__ __forceinline__ void mma_f16(float4& d,
                                        uint32_t a0, uint32_t a1, uint32_t a2, uint32_t a3,
                                        uint32_t b0, uint32_t b1) {
    asm volatile(
        "mma.sync.aligned.m16n8k16.row.col.f32.f16.f16.f32 "
        "{%0,%1,%2,%3}, {%4,%5,%6,%7}, {%8,%9}, {%0,%1,%2,%3};"
        : "+f"(d.x), "+f"(d.y), "+f"(d.z), "+f"(d.w)
        : "r"(a0), "r"(a1), "r"(a2), "r"(a3), "r"(b0), "r"(b1));
}

// pack two floats -> half2 in a b32 reg (lo in low half)
__device__ __forceinline__ uint32_t pack2h(float lo, float hi) {
    uint32_t r;
    asm("cvt.rn.f16x2.f32 %0, %1, %2;" : "=r"(r) : "f"(hi), "f"(lo));
    return r;
}
__device__ __forceinline__ float h2f_rn(float x) {   // fp16 round-trip
    return __half2float(__float2half_rn(x));
}

// ---------------- Kernel A: LayerNorm + (bias projection + mask) -----------
__global__ __launch_bounds__(256)
void ln_bias_kernel(const float* __restrict__ x,
                    const float* __restrict__ mask,
                    const float* __restrict__ lnw,
                    const float* __restrict__ lnb,
                    const float* __restrict__ Wb) {
    int lane = threadIdx.x & 31;
    int row  = blockIdx.x * 8 + (threadIdx.x >> 5);
    const float* xr = x + (size_t)row * DM;

    float v0 = xr[lane], v1 = xr[lane+32], v2 = xr[lane+64], v3 = xr[lane+96];
    float s = v0 + v1 + v2 + v3;
    #pragma unroll
    for (int o = 16; o; o >>= 1) s += __shfl_xor_sync(0xffffffffu, s, o);
    float mu = s * (1.0f/128.0f);
    float d0 = v0-mu, d1 = v1-mu, d2 = v2-mu, d3 = v3-mu;
    float qq = d0*d0 + d1*d1 + d2*d2 + d3*d3;
    #pragma unroll
    for (int o = 16; o; o >>= 1) qq += __shfl_xor_sync(0xffffffffu, qq, o);
    float inv = rsqrtf(qq * (1.0f/128.0f) + 1e-5f);

    float n0 = fmaf(d0*inv, lnw[lane   ], lnb[lane   ]);
    float n1 = fmaf(d1*inv, lnw[lane+32], lnb[lane+32]);
    float n2 = fmaf(d2*inv, lnw[lane+64], lnb[lane+64]);
    float n3 = fmaf(d3*inv, lnw[lane+96], lnb[lane+96]);

    float* xo = g_xn + (size_t)row * DM;
    xo[lane] = n0; xo[lane+32] = n1; xo[lane+64] = n2; xo[lane+96] = n3;

    float mval = mask[row];
    #pragma unroll
    for (int hh = 0; hh < NH; hh++) {
        const float* wb = Wb + hh * DM;
        float dot = n0*wb[lane] + n1*wb[lane+32] + n2*wb[lane+64] + n3*wb[lane+96];
        #pragma unroll
        for (int o = 16; o; o >>= 1) dot += __shfl_xor_sync(0xffffffffu, dot, o);
        if (lane == 0) g_bm[(size_t)hh * NROWS + row] = dot + mval;
    }
}

// ---------------- Kernel B: mma.sync tf32 GEMM ------------------------------
#define LDA 132
#define GEMM_SMEM (2 * 128 * LDA * 4)

__global__ __launch_bounds__(256, 1)
void gemm_tf32_kernel(const float* __restrict__ Wq, const float* __restrict__ Wk,
                      const float* __restrict__ Wv, const float* __restrict__ Wg,
                      const float* __restrict__ Wo, float* __restrict__ out, int mode) {
    uint32_t* As = (uint32_t*)smem_raw;        // [128][LDA] tf32
    uint32_t* Ws = As + 128 * LDA;             // [128][LDA] tf32

    int tid = threadIdx.x, wid = tid >> 5, lane = tid & 31;
    int m0 = blockIdx.x * 128;
    int lr = lane >> 2, lc = lane & 3;
    int wr = wid & 3;
    int wc = wid >> 2;

    if (mode == 0) {
        #pragma unroll
        for (int t = tid; t < 128 * 32; t += 256) {
            int row = t >> 5, c4 = (t & 31) * 4;
            float4 v = *(const float4*)(g_xn + (size_t)(m0 + row) * DM + c4);
            uint32_t* d = As + row * LDA + c4;
            d[0] = f2tf32(v.x); d[1] = f2tf32(v.y); d[2] = f2tf32(v.z); d[3] = f2tf32(v.w);
        }
    } else {
        #pragma unroll
        for (int t = tid; t < 128 * 32; t += 256) {
            int row = t >> 5, c4 = (t & 31) * 4;
            size_t gi = (size_t)(m0 + row) * DM + c4;
            float4 ov = *(const float4*)(g_o + gi);
            float4 gv = *(const float4*)(g_g + gi);
            uint32_t* d = As + row * LDA + c4;
            d[0] = f2tf32(ov.x / (1.0f + __expf(-gv.x)));
            d[1] = f2tf32(ov.y / (1.0f + __expf(-gv.y)));
            d[2] = f2tf32(ov.z / (1.0f + __expf(-gv.z)));
            d[3] = f2tf32(ov.w / (1.0f + __expf(-gv.w)));
        }
    }

    const float* Wsrc[4] = {Wq, Wk, Wv, Wg};
    int nW = (mode == 0) ? 4 : 1;

    for (int w = 0; w < nW; w++) {
        const float* W = (mode == 1) ? Wo : Wsrc[w];
        #pragma unroll
        for (int t = tid; t < 128 * 32; t += 256) {
            int row = t >> 5, c4 = (t & 31) * 4;
            float4 v = *(const float4*)(W + (size_t)row * DM + c4);
            uint32_t* d = Ws + row * LDA + c4;
            d[0] = f2tf32(v.x); d[1] = f2tf32(v.y); d[2] = f2tf32(v.z); d[3] = f2tf32(v.w);
        }
        __syncthreads();

        float4 acc[2][8];
        #pragma unroll
        for (int mt = 0; mt < 2; mt++)
            #pragma unroll
            for (int nt = 0; nt < 8; nt++) acc[mt][nt] = make_float4(0.f, 0.f, 0.f, 0.f);

        const uint32_t* Ab = As + (wr * 32 + lr) * LDA + lc;
        const uint32_t* Bb = Ws + (wc * 64 + lr) * LDA + lc;

        #pragma unroll
        for (int ks = 0; ks < 16; ks++) {
            int k0 = ks * 8;
            uint32_t a[2][4], b[8][2];
            #pragma unroll
            for (int mt = 0; mt < 2; mt++) {
                const uint32_t* p = Ab + mt * 16 * LDA + k0;
                a[mt][0] = p[0];
                a[mt][1] = p[8 * LDA];
                a[mt][2] = p[4];
                a[mt][3] = p[8 * LDA + 4];
            }
            #pragma unroll
            for (int nt = 0; nt < 8; nt++) {
                const uint32_t* p = Bb + nt * 8 * LDA + k0;
                b[nt][0] = p[0];
                b[nt][1] = p[4];
            }
            #pragma unroll
            for (int mt = 0; mt < 2; mt++)
                #pragma unroll
                for (int nt = 0; nt < 8; nt++)
                    mma_tf32(acc[mt][nt], a[mt][0], a[mt][1], a[mt][2], a[mt][3],
                             b[nt][0], b[nt][1]);
        }

        #pragma unroll
        for (int mt = 0; mt < 2; mt++) {
            int m = m0 + wr * 32 + mt * 16 + lr;
            #pragma unroll
            for (int nt = 0; nt < 8; nt++) {
                int e = wc * 64 + nt * 8 + 2 * lc;
                float2 lo = make_float2(acc[mt][nt].x, acc[mt][nt].y);
                float2 hi = make_float2(acc[mt][nt].z, acc[mt][nt].w);
                if (mode == 1) {
                    *(float2*)(out + (size_t)m * DM + e)       = lo;
                    *(float2*)(out + (size_t)(m + 8) * DM + e) = hi;
                } else if (w == 3) {
                    *(float2*)(g_g + (size_t)m * DM + e)       = lo;
                    *(float2*)(g_g + (size_t)(m + 8) * DM + e) = hi;
                } else {
                    float* dst3 = (w == 0) ? g_q : (w == 1) ? g_k : g_v;
                    int h = e >> 5, dh = e & 31;
                    int b0i = m >> 8, q0i = m & 255;
                    int b1i = (m + 8) >> 8, q1i = (m + 8) & 255;
                    *(float2*)(dst3 + (((size_t)(b0i * NH + h)) * SS + q0i) * HD + dh) = lo;
                    *(float2*)(dst3 + (((size_t)(b1i * NH + h)) * SS + q1i) * HD + dh) = hi;
                }
            }
        }
        __syncthreads();
    }
}

// ---------------- Kernel C: FA2-style fp16 split attention per (b,h) -------
// smem halves: Kh[256][40], Kl[256][40], Vh^T[32][264], Vl^T[32][264]
#define AT_KL 10240
#define AT_VH 20480
#define AT_VL 28928
#define ATTN_SMEM ((28928 + 8448) * 2)   // 74752 B

__global__ __launch_bounds__(256, 1)
void attn_fa_kernel() {
    __half* sh = (__half*)smem_raw;
    __half* Kh = sh;
    __half* Kl = sh + AT_KL;
    __half* Vh = sh + AT_VH;
    __half* Vl = sh + AT_VL;

    int bh = blockIdx.x, b = bh >> 2, h = bh & 3;
    const float* Qg = g_q + (size_t)bh * (SS * HD);
    const float* Kg = g_k + (size_t)bh * (SS * HD);
    const float* Vg = g_v + (size_t)bh * (SS * HD);

    int tid = threadIdx.x, warp = tid >> 5, lane = tid & 31;
    int lr = lane >> 2, lc = lane & 3;

    // ---- stage K hi/lo [key][dim] (stride 40) and V^T hi/lo [dim][key] (264)
    for (int i = tid; i < SS * HD; i += 256) {
        int key = i >> 5, d = i & 31;
        float kv = Kg[i];
        __half kh = __float2half_rn(kv);
        Kh[key * 40 + d] = kh;
        Kl[key * 40 + d] = __float2half_rn(kv - __half2float(kh));
        float vv = Vg[i];
        __half vh = __float2half_rn(vv);
        Vh[d * 264 + key] = vh;
        Vl[d * 264 + key] = __float2half_rn(vv - __half2float(vh));
    }
    __syncthreads();

    const uint32_t* Khw = (const uint32_t*)Kh;   // word stride 20/row
    const uint32_t* Klw = (const uint32_t*)Kl;
    const uint32_t* Vhw = (const uint32_t*)Vh;   // word stride 132/row
    const uint32_t* Vlw = (const uint32_t*)Vl;

    for (int qt = 0; qt < 2; qt++) {
        int r0 = qt * 128 + warp * 16 + lr;      // rows r0 (.x/.y) and r0+8 (.z/.w)

        // ---- Q fragments (pre-scaled, fp16 hi/lo split) ----
        uint32_t qh[2][4], ql[2][4];
        #pragma unroll
        for (int t = 0; t < 2; t++) {
            #pragma unroll
            for (int idx = 0; idx < 4; idx++) {
                int row = (idx & 1) ? r0 + 8 : r0;
                int dim = t * 16 + 2 * lc + ((idx >= 2) ? 8 : 0);
                float2 qv = *(const float2*)(Qg + (size_t)row * HD + dim);
                float qx = qv.x * 0.17677669529663687f;
                float qy = qv.y * 0.17677669529663687f;
                float hx = h2f_rn(qx), hy = h2f_rn(qy);
                qh[t][idx] = pack2h(hx, hy);
                ql[t][idx] = pack2h(qx - hx, qy - hy);
            }
        }

        // ---- S = Q K^T : 3-pass fp16 (qh*kh + qh*kl + ql*kh) ----
        float4 acc[32];
        #pragma unroll
        for (int j = 0; j < 32; j++) acc[j] = make_float4(0.f, 0.f, 0.f, 0.f);

        #pragma unroll
        for (int j = 0; j < 32; j++) {
            int kw = (j * 8 + lr) * 20 + lc;
            uint32_t kh00 = Khw[kw],     kh01 = Khw[kw + 4];
            uint32_t kh10 = Khw[kw + 8], kh11 = Khw[kw + 12];
            uint32_t kl00 = Klw[kw],     kl01 = Klw[kw + 4];
            uint32_t kl10 = Klw[kw + 8], kl11 = Klw[kw + 12];
            mma_f16(acc[j], qh[0][0], qh[0][1], qh[0][2], qh[0][3], kh00, kh01);
            mma_f16(acc[j], qh[1][0], qh[1][1], qh[1][2], qh[1][3], kh10, kh11);
            mma_f16(acc[j], qh[0][0], qh[0][1], qh[0][2], qh[0][3], kl00, kl01);
            mma_f16(acc[j], qh[1][0], qh[1][1], qh[1][2], qh[1][3], kl10, kl11);
            mma_f16(acc[j], ql[0][0], ql[0][1], ql[0][2], ql[0][3], kh00, kh01);
            mma_f16(acc[j], ql[1][0], ql[1][1], ql[1][2], ql[1][3], kh10, kh11);
        }

        // ---- bias+mask add, softmax over 256 cols (quad-local reduction) ---
        const float* bm0 = g_bm + (size_t)h * NROWS + (size_t)r0 * SS;
        const float* bm1 = bm0 + 8 * SS;
        float mx0 = -3.0e38f, mx1 = -3.0e38f;
        #pragma unroll
        for (int j = 0; j < 32; j++) {
            float2 b0 = *(const float2*)(bm0 + j * 8 + 2 * lc);
            float2 b1 = *(const float2*)(bm1 + j * 8 + 2 * lc);
            acc[j].x += b0.x; acc[j].y += b0.y;
            acc[j].z += b1.x; acc[j].w += b1.y;
            mx0 = fmaxf(mx0, fmaxf(acc[j].x, acc[j].y));
            mx1 = fmaxf(mx1, fmaxf(acc[j].z, acc[j].w));
        }
        mx0 = fmaxf(mx0, __shfl_xor_sync(0xffffffffu, mx0, 1));
        mx0 = fmaxf(mx0, __shfl_xor_sync(0xffffffffu, mx0, 2));
        mx1 = fmaxf(mx1, __shfl_xor_sync(0xffffffffu, mx1, 1));
        mx1 = fmaxf(mx1, __shfl_xor_sync(0xffffffffu, mx1, 2));
        float s0 = 0.f, s1 = 0.f;
        #pragma unroll
        for (int j = 0; j < 32; j++) {
            acc[j].x = __expf(acc[j].x - mx0); s0 += acc[j].x;
            acc[j].y = __expf(acc[j].y - mx0); s0 += acc[j].y;
            acc[j].z = __expf(acc[j].z - mx1); s1 += acc[j].z;
            acc[j].w = __expf(acc[j].w - mx1); s1 += acc[j].w;
        }
        s0 += __shfl_xor_sync(0xffffffffu, s0, 1);
        s0 += __shfl_xor_sync(0xffffffffu, s0, 2);
        s1 += __shfl_xor_sync(0xffffffffu, s1, 1);
        s1 += __shfl_xor_sync(0xffffffffu, s1, 2);
        float i0 = 1.0f / s0, i1 = 1.0f / s1;
        #pragma unroll
        for (int j = 0; j < 32; j++) {
            acc[j].x *= i0; acc[j].y *= i0; acc[j].z *= i1; acc[j].w *= i1;
        }

        // ---- O = P V : 3-pass (ph*vh + ph*vl + pl*vh), P from registers ----
        float4 oacc[4];
        #pragma unroll
        for (int dn = 0; dn < 4; dn++) oacc[dn] = make_float4(0.f, 0.f, 0.f, 0.f);

        #pragma unroll
        for (int t = 0; t < 16; t++) {
            float4 c0 = acc[2 * t], c1 = acc[2 * t + 1];
            float h00 = h2f_rn(c0.x), h01 = h2f_rn(c0.y);
            float h02 = h2f_rn(c0.z), h03 = h2f_rn(c0.w);
            float h10 = h2f_rn(c1.x), h11 = h2f_rn(c1.y);
            float h12 = h2f_rn(c1.z), h13 = h2f_rn(c1.w);
            uint32_t ah0 = pack2h(h00, h01), ah1 = pack2h(h02, h03);
            uint32_t ah2 = pack2h(h10, h11), ah3 = pack2h(h12, h13);
            uint32_t al0 = pack2h(c0.x - h00, c0.y - h01);
            uint32_t al1 = pack2h(c0.z - h02, c0.w - h03);
            uint32_t al2 = pack2h(c1.x - h10, c1.y - h11);
            uint32_t al3 = pack2h(c1.z - h12, c1.w - h13);
            #pragma unroll
            for (int dn = 0; dn < 4; dn++) {
                int vw = (dn * 8 + lr) * 132 + 8 * t + lc;
                uint32_t vb0 = Vhw[vw], vb1 = Vhw[vw + 4];
                uint32_t wb0 = Vlw[vw], wb1 = Vlw[vw + 4];
                mma_f16(oacc[dn], ah0, ah1, ah2, ah3, vb0, vb1);
                mma_f16(oacc[dn], ah0, ah1, ah2, ah3, wb0, wb1);
                mma_f16(oacc[dn], al0, al1, al2, al3, vb0, vb1);
            }
        }

        // ---- store O: rows r0, r0+8; dims dn*8 + 2lc,+1 ----
        float* o0 = g_o + ((size_t)(b * 256 + r0) * NH + h) * HD;
        float* o1 = g_o + ((size_t)(b * 256 + r0 + 8) * NH + h) * HD;
        #pragma unroll
        for (int dn = 0; dn < 4; dn++) {
            *(float2*)(o0 + dn * 8 + 2 * lc) = make_float2(oacc[dn].x, oacc[dn].y);
            *(float2*)(o1 + dn * 8 + 2 * lc) = make_float2(oacc[dn].z, oacc[dn].w);
        }
    }
}

// ---------------- launch ----------------------------------------------------
extern "C" void kernel_launch(void* const* d_in, const int* in_sizes, int n_in,
                              void* d_out, int out_size) {
    const float* x    = (const float*)d_in[0];
    const float* mask = (const float*)d_in[1];
    const float* lnw  = (const float*)d_in[2];
    const float* lnb  = (const float*)d_in[3];
    const float* Wb   = (const float*)d_in[4];
    const float* Wq   = (const float*)d_in[5];
    const float* Wk   = (const float*)d_in[6];
    const float* Wv   = (const float*)d_in[7];
    const float* Wg   = (const float*)d_in[8];
    const float* Wo   = (const float*)d_in[9];
    float* out = (float*)d_out;

    cudaFuncSetAttribute(gemm_tf32_kernel, cudaFuncAttributeMaxDynamicSharedMemorySize, GEMM_SMEM);
    cudaFuncSetAttribute(attn_fa_kernel,   cudaFuncAttributeMaxDynamicSharedMemorySize, ATTN_SMEM);

    ln_bias_kernel<<<NROWS / 8, 256>>>(x, mask, lnw, lnb, Wb);
    gemm_tf32_kernel<<<NROWS / 128, 256, GEMM_SMEM>>>(Wq, Wk, Wv, Wg, Wo, out, 0);
    attn_fa_kernel<<<SS * NH, 256, ATTN_SMEM>>>();
    gemm_tf32_kernel<<<NROWS / 128, 256, GEMM_SMEM>>>(Wq, Wk, Wv, Wg, Wo, out, 1);
}